// round 9
// baseline (speedup 1.0000x reference)
#include <cuda_runtime.h>

typedef unsigned long long u64;
#define WARPS 4
#define PTS 2
#define FULLMASK 0xffffffffu

__device__ float2 g_wuni[2048];   // interleaved {w_un, wd_un}

__constant__ __align__(16) float c_wvn[48];
__constant__ __align__(16) float c_wdvn[48];
__constant__ __align__(16) float c_wh1[128];
__constant__ __align__(16) float c_wh2[64];
__constant__ __align__(16) float c_bh2[8];

__global__ void prep_wuni(const float* __restrict__ w_un, const float* __restrict__ wd_un) {
    const int i = blockIdx.x * blockDim.x + threadIdx.x;
    if (i < 2048) g_wuni[i] = make_float2(w_un[i], wd_un[i]);
}

__device__ __forceinline__ u64 pk2(float x, float y) {
    u64 r; asm("mov.b64 %0,{%1,%2};" : "=l"(r) : "f"(x), "f"(y)); return r;
}
__device__ __forceinline__ void upk2(u64 v, float& x, float& y) {
    asm("mov.b64 {%0,%1},%2;" : "=f"(x), "=f"(y) : "l"(v));
}
__device__ __forceinline__ u64 fma2(u64 a, u64 b, u64 c) {
    u64 d; asm("fma.rn.f32x2 %0,%1,%2,%3;" : "=l"(d) : "l"(a), "l"(b), "l"(c)); return d;
}
__device__ __forceinline__ u64 mul2(u64 a, u64 b) {
    u64 d; asm("mul.rn.f32x2 %0,%1,%2;" : "=l"(d) : "l"(a), "l"(b)); return d;
}

__global__ void __launch_bounds__(128, 6) arek(
    const float* __restrict__ q_pts, const float* __restrict__ s_pts,
    const int*   __restrict__ nbr,
    const float* __restrict__ wb,
    const float* __restrict__ wd_relu,
    float* __restrict__ out, int N)
{
    const float BN = 0.99999500003749968f;   // 1/sqrt(1+1e-5)
    const float BN2 = BN * BN;

    __shared__ float s_wb[768];
    // ---- per-warp scratch, packed over the 2 points; rows padded to 80B ----
    __shared__ __align__(16) u64 s_local2[WARPS][16][10];  // comps 0..8 = p,c,r xyz
    __shared__ __align__(16) u64 s_score2[WARPS][16][10];  // comps 0..7 = scores (unnormalized)
    __shared__ u64 s_feat2 [WARPS][32][3];                 // [h][comp] -> (p0,p1)

    const int tid = threadIdx.x;
    #pragma unroll
    for (int i = tid; i < 768; i += 128) s_wb[i] = wb[i];
    __syncthreads();

    const int warp = tid >> 5, lane = tid & 31;
    const int n0 = blockIdx.x * (WARPS * PTS) + warp * PTS;
    if (n0 >= N) return;

    // ================= Phase 1: lane = (p, k), channel-pair packed =================
    {
        const int pp = lane >> 4;            // point within pair
        const int k  = lane & 15;            // neighbor
        const int n  = (n0 + pp < N) ? (n0 + pp) : (N - 1);

        const float qx = q_pts[n*3+0], qy = q_pts[n*3+1], qz = q_pts[n*3+2];
        const int idx = nbr[n*16 + k];
        const float px = s_pts[idx*3+0] - qx;
        const float py = s_pts[idx*3+1] - qy;
        const float pz = s_pts[idx*3+2] - qz;

        float sx = px, sy = py, sz = pz;
        #pragma unroll
        for (int off = 1; off < 16; off <<= 1) {
            sx += __shfl_xor_sync(FULLMASK, sx, off);
            sy += __shfl_xor_sync(FULLMASK, sy, off);
            sz += __shfl_xor_sync(FULLMASK, sz, off);
        }
        const float cx = sx * (1.0f/16.0f);
        const float cy = sy * (1.0f/16.0f);
        const float cz = sz * (1.0f/16.0f);

        const float rx = py*cz - pz*cy;
        const float ry = pz*cx - px*cz;
        const float rz = px*cy - py*cx;

        ((float*)&s_local2[warp][k][0])[pp] = px;
        ((float*)&s_local2[warp][k][1])[pp] = py;
        ((float*)&s_local2[warp][k][2])[pp] = pz;
        ((float*)&s_local2[warp][k][3])[pp] = cx;
        ((float*)&s_local2[warp][k][4])[pp] = cy;
        ((float*)&s_local2[warp][k][5])[pp] = cz;
        ((float*)&s_local2[warp][k][6])[pp] = rx;
        ((float*)&s_local2[warp][k][7])[pp] = ry;
        ((float*)&s_local2[warp][k][8])[pp] = rz;

        const u64 PX = pk2(px,px), PY = pk2(py,py), PZ = pk2(pz,pz);
        const u64 CX = pk2(cx,cx), CY = pk2(cy,cy), CZ = pk2(cz,cz);
        const u64 RX = pk2(rx,rx), RY = pk2(ry,ry), RZ = pk2(rz,rz);

        // h1 accum over o-pairs; channel loop packed over (2pc, 2pc+1)
        // NOTE: BN deferred — p here is unscaled; vn_act linear in p, sn = BN*||.||,
        // folded as BN^2 into the h1 result below.
        u64 h1p[4] = {0,0,0,0};
        #pragma unroll
        for (int pc = 0; pc < 8; pc++) {
            const u64 wA = *(const u64*)&c_wvn [     2*pc];
            const u64 wB = *(const u64*)&c_wvn [16 + 2*pc];
            const u64 wC = *(const u64*)&c_wvn [32 + 2*pc];
            const u64 uA = *(const u64*)&c_wdvn[     2*pc];
            const u64 uB = *(const u64*)&c_wdvn[16 + 2*pc];
            const u64 uC = *(const u64*)&c_wdvn[32 + 2*pc];
            const u64 p0 = fma2(PX, wA, fma2(CX, wB, mul2(RX, wC)));
            const u64 p1 = fma2(PY, wA, fma2(CY, wB, mul2(RY, wC)));
            const u64 p2 = fma2(PZ, wA, fma2(CZ, wB, mul2(RZ, wC)));
            const u64 d0 = fma2(PX, uA, fma2(CX, uB, mul2(RX, uC)));
            const u64 d1 = fma2(PY, uA, fma2(CY, uB, mul2(RY, uC)));
            const u64 d2 = fma2(PZ, uA, fma2(CZ, uB, mul2(RZ, uC)));
            const u64 dot2 = fma2(p0, d0, fma2(p1, d1, mul2(p2, d2)));
            const u64 dsq2 = fma2(d0, d0, fma2(d1, d1, mul2(d2, d2)));
            float dta, dtb, dqa, dqb;
            upk2(dot2, dta, dtb); upk2(dsq2, dqa, dqb);
            const float nfa = (dta >= 0.0f) ? 0.0f : (-0.8f * __fdividef(dta, dqa + 1e-6f));
            const float nfb = (dtb >= 0.0f) ? 0.0f : (-0.8f * __fdividef(dtb, dqb + 1e-6f));
            const u64 nf = pk2(nfa, nfb);
            const u64 s0 = fma2(nf, d0, p0);
            const u64 s1 = fma2(nf, d1, p1);
            const u64 s2 = fma2(nf, d2, p2);
            const u64 nn = fma2(s0, s0, fma2(s1, s1, mul2(s2, s2)));
            float na, nb; upk2(nn, na, nb);
            const float sa = sqrtf(na), sb = sqrtf(nb);
            const u64 SA = pk2(sa, sa), SB = pk2(sb, sb);
            // rows 2pc and 2pc+1 of w_h1 (8 floats each = 2 u64x2, 16B-aligned)
            const ulonglong2* r0 = (const ulonglong2*)&c_wh1[(2*pc  )*8];
            const ulonglong2* r1 = (const ulonglong2*)&c_wh1[(2*pc+1)*8];
            const ulonglong2 r0a = r0[0], r0b = r0[1];
            const ulonglong2 r1a = r1[0], r1b = r1[1];
            h1p[0] = fma2(SA, r0a.x, fma2(SB, r1a.x, h1p[0]));
            h1p[1] = fma2(SA, r0a.y, fma2(SB, r1a.y, h1p[1]));
            h1p[2] = fma2(SA, r0b.x, fma2(SB, r1b.x, h1p[2]));
            h1p[3] = fma2(SA, r0b.y, fma2(SB, r1b.y, h1p[3]));
        }
        const u64 BN2d = pk2(BN2, BN2);
        float h1s[8];
        #pragma unroll
        for (int o2 = 0; o2 < 4; o2++) {
            float ea, eb; upk2(mul2(h1p[o2], BN2d), ea, eb);
            h1s[2*o2]   = fmaxf(0.0f, ea);
            h1s[2*o2+1] = fmaxf(0.0f, eb);
        }

        // h2 accum over o-pairs with raw c_wh2 rows
        u64 h2p[4] = { *(const u64*)&c_bh2[0], *(const u64*)&c_bh2[2],
                       *(const u64*)&c_bh2[4], *(const u64*)&c_bh2[6] };
        #pragma unroll
        for (int c = 0; c < 8; c++) {
            const ulonglong2* wr = (const ulonglong2*)&c_wh2[c*8];
            const ulonglong2 wa = wr[0], wbq = wr[1];
            const u64 SC = pk2(h1s[c], h1s[c]);
            h2p[0] = fma2(SC, wa.x,  h2p[0]);
            h2p[1] = fma2(SC, wa.y,  h2p[1]);
            h2p[2] = fma2(SC, wbq.x, h2p[2]);
            h2p[3] = fma2(SC, wbq.y, h2p[3]);
        }
        float h2[8];
        upk2(h2p[0], h2[0], h2[1]); upk2(h2p[1], h2[2], h2[3]);
        upk2(h2p[2], h2[4], h2[5]); upk2(h2p[3], h2[6], h2[7]);
        float m = h2[0];
        #pragma unroll
        for (int o = 1; o < 8; o++) m = fmaxf(m, h2[o]);
        // softmax denominator dropped: per-k positive scale cancels in the
        // per-(h,k) normalization of phase 2.
        #pragma unroll
        for (int o = 0; o < 8; o++)
            ((float*)&s_score2[warp][k][o])[pp] = __expf(h2[o] - m);
    }
    __syncwarp();

    // ======= Phase 2: correlation, lane = channel h, packed over the 2 points =======
    u64 wbd0[8], wbd1[8], wbd2[8];
    #pragma unroll
    for (int ks = 0; ks < 8; ks++) {
        const float w0 = s_wb[      ks*32 + lane];
        const float w1 = s_wb[256 + ks*32 + lane];
        const float w2 = s_wb[512 + ks*32 + lane];
        wbd0[ks] = pk2(w0, w0); wbd1[ks] = pk2(w1, w1); wbd2[ks] = pk2(w2, w2);
    }
    {
        u64 fa0 = 0, fa1 = 0, fa2 = 0;
        #pragma unroll
        for (int kk = 0; kk < 16; kk++) {
            const ulonglong2* scv = (const ulonglong2*)s_score2[warp][kk];
            const ulonglong2 sAB = scv[0], sCD = scv[1], sEF = scv[2], sGH = scv[3];
            u64 we0 = mul2(sAB.x, wbd0[0]);
            u64 we1 = mul2(sAB.x, wbd1[0]);
            u64 we2 = mul2(sAB.x, wbd2[0]);
            we0 = fma2(sAB.y, wbd0[1], we0); we1 = fma2(sAB.y, wbd1[1], we1); we2 = fma2(sAB.y, wbd2[1], we2);
            we0 = fma2(sCD.x, wbd0[2], we0); we1 = fma2(sCD.x, wbd1[2], we1); we2 = fma2(sCD.x, wbd2[2], we2);
            we0 = fma2(sCD.y, wbd0[3], we0); we1 = fma2(sCD.y, wbd1[3], we1); we2 = fma2(sCD.y, wbd2[3], we2);
            we0 = fma2(sEF.x, wbd0[4], we0); we1 = fma2(sEF.x, wbd1[4], we1); we2 = fma2(sEF.x, wbd2[4], we2);
            we0 = fma2(sEF.y, wbd0[5], we0); we1 = fma2(sEF.y, wbd1[5], we1); we2 = fma2(sEF.y, wbd2[5], we2);
            we0 = fma2(sGH.x, wbd0[6], we0); we1 = fma2(sGH.x, wbd1[6], we1); we2 = fma2(sGH.x, wbd2[6], we2);
            we0 = fma2(sGH.y, wbd0[7], we0); we1 = fma2(sGH.y, wbd1[7], we1); we2 = fma2(sGH.y, wbd2[7], we2);

            const ulonglong2* Lv = (const ulonglong2*)s_local2[warp][kk];
            const ulonglong2 L01 = Lv[0], L23 = Lv[1], L45 = Lv[2], L67 = Lv[3];
            const u64 L8 = s_local2[warp][kk][8];
            const u64 q0 = fma2(L01.x, we0, fma2(L23.y, we1, mul2(L67.x, we2)));
            const u64 q1 = fma2(L01.y, we0, fma2(L45.x, we1, mul2(L67.y, we2)));
            const u64 q2 = fma2(L23.x, we0, fma2(L45.y, we1, mul2(L8,    we2)));
            const u64 nn = fma2(q0, q0, fma2(q1, q1, mul2(q2, q2)));
            float n0f, n1f; upk2(nn, n0f, n1f);
            const u64 iv = pk2(rsqrtf(fmaxf(n0f, 1e-24f)), rsqrtf(fmaxf(n1f, 1e-24f)));
            fa0 = fma2(q0, iv, fa0);
            fa1 = fma2(q1, iv, fa1);
            fa2 = fma2(q2, iv, fa2);
        }
        const u64 SC = pk2(1.0f/16.0f, 1.0f/16.0f);
        s_feat2[warp][lane][0] = mul2(fa0, SC);
        s_feat2[warp][lane][1] = mul2(fa1, SC);
        s_feat2[warp][lane][2] = mul2(fa2, SC);
    }
    __syncwarp();

    // ======= Phase 3a: VNLeakyReLU(32->32), packed over points =======
    {
        u64 f0 = s_feat2[warp][lane][0];
        u64 f1 = s_feat2[warp][lane][1];
        u64 f2 = s_feat2[warp][lane][2];
        u64 g0 = 0, g1 = 0, g2 = 0;
        #pragma unroll
        for (int h = 0; h < 32; h++) {
            const float w = __ldg(wd_relu + h*32 + lane);
            const u64 w2 = pk2(w, w);
            g0 = fma2(s_feat2[warp][h][0], w2, g0);
            g1 = fma2(s_feat2[warp][h][1], w2, g1);
            g2 = fma2(s_feat2[warp][h][2], w2, g2);
        }
        const u64 dot2 = fma2(f0, g0, fma2(f1, g1, mul2(f2, g2)));
        const u64 dsq2 = fma2(g0, g0, fma2(g1, g1, mul2(g2, g2)));
        float dta, dtb, dqa, dqb;
        upk2(dot2, dta, dtb); upk2(dsq2, dqa, dqb);
        const float nfa = (dta >= 0.0f) ? 0.0f : (-0.8f * __fdividef(dta, dqa + 1e-6f));
        const float nfb = (dtb >= 0.0f) ? 0.0f : (-0.8f * __fdividef(dtb, dqb + 1e-6f));
        const u64 nf = pk2(nfa, nfb);
        __syncwarp();
        s_feat2[warp][lane][0] = fma2(nf, g0, f0);
        s_feat2[warp][lane][1] = fma2(nf, g1, f1);
        s_feat2[warp][lane][2] = fma2(nf, g2, f2);
    }
    __syncwarp();

    // ======= Phase 3b: VNLinearLeakyReLU(32->64), interleaved weights, packed =======
    {
        u64 ax=0, ay=0, az=0, bx=0, by=0, bz=0;   // j = lane
        u64 Ax=0, Ay=0, Az=0, Bx=0, By=0, Bz=0;   // j = lane + 32
        #pragma unroll
        for (int h = 0; h < 32; h++) {
            const float2 wv0 = g_wuni[h*64 + lane];
            const float2 wv1 = g_wuni[h*64 + lane + 32];
            const u64 F0 = s_feat2[warp][h][0];
            const u64 F1 = s_feat2[warp][h][1];
            const u64 F2 = s_feat2[warp][h][2];
            const u64 wa0d = pk2(wv0.x, wv0.x), wd0d = pk2(wv0.y, wv0.y);
            const u64 wa1d = pk2(wv1.x, wv1.x), wd1d = pk2(wv1.y, wv1.y);
            ax = fma2(F0, wa0d, ax); ay = fma2(F1, wa0d, ay); az = fma2(F2, wa0d, az);
            bx = fma2(F0, wd0d, bx); by = fma2(F1, wd0d, by); bz = fma2(F2, wd0d, bz);
            Ax = fma2(F0, wa1d, Ax); Ay = fma2(F1, wa1d, Ay); Az = fma2(F2, wa1d, Az);
            Bx = fma2(F0, wd1d, Bx); By = fma2(F1, wd1d, By); Bz = fma2(F2, wd1d, Bz);
        }
        float axp[2], ayp[2], azp[2], bxp[2], byp[2], bzp[2];
        float Axp[2], Ayp[2], Azp[2], Bxp[2], Byp[2], Bzp[2];
        upk2(ax, axp[0], axp[1]); upk2(ay, ayp[0], ayp[1]); upk2(az, azp[0], azp[1]);
        upk2(bx, bxp[0], bxp[1]); upk2(by, byp[0], byp[1]); upk2(bz, bzp[0], bzp[1]);
        upk2(Ax, Axp[0], Axp[1]); upk2(Ay, Ayp[0], Ayp[1]); upk2(Az, Azp[0], Azp[1]);
        upk2(Bx, Bxp[0], Bxp[1]); upk2(By, Byp[0], Byp[1]); upk2(Bz, Bzp[0], Bzp[1]);
        #pragma unroll
        for (int p = 0; p < PTS; p++) {
            if (n0 + p >= N) break;
            const int n = n0 + p;
            {
                const int j = lane;
                const float x0 = BN*axp[p], x1 = BN*ayp[p], x2 = BN*azp[p];
                const float dt = x0*bxp[p] + x1*byp[p] + x2*bzp[p];
                const float dq = bxp[p]*bxp[p] + byp[p]*byp[p] + bzp[p]*bzp[p];
                const float fc = (dt >= 0.0f) ? 0.0f : (0.8f * __fdividef(dt, dq + 1e-6f));
                out[n*192 + j*3 + 0] = x0 - fc*bxp[p];
                out[n*192 + j*3 + 1] = x1 - fc*byp[p];
                out[n*192 + j*3 + 2] = x2 - fc*bzp[p];
            }
            {
                const int j = lane + 32;
                const float x0 = BN*Axp[p], x1 = BN*Ayp[p], x2 = BN*Azp[p];
                const float dt = x0*Bxp[p] + x1*Byp[p] + x2*Bzp[p];
                const float dq = Bxp[p]*Bxp[p] + Byp[p]*Byp[p] + Bzp[p]*Bzp[p];
                const float fc = (dt >= 0.0f) ? 0.0f : (0.8f * __fdividef(dt, dq + 1e-6f));
                out[n*192 + j*3 + 0] = x0 - fc*Bxp[p];
                out[n*192 + j*3 + 1] = x1 - fc*Byp[p];
                out[n*192 + j*3 + 2] = x2 - fc*Bzp[p];
            }
        }
    }
}

extern "C" void kernel_launch(void* const* d_in, const int* in_sizes, int n_in,
                              void* d_out, int out_size) {
    const float* q_pts   = (const float*)d_in[0];
    const float* s_pts   = (const float*)d_in[1];
    const int*   nbr     = (const int*)  d_in[3];
    const float* wb      = (const float*)d_in[4];
    const float* w_vn    = (const float*)d_in[5];
    const float* wd_vn   = (const float*)d_in[6];
    const float* w_h1    = (const float*)d_in[7];
    const float* w_h2    = (const float*)d_in[8];
    const float* b_h2    = (const float*)d_in[9];
    const float* wd_relu = (const float*)d_in[10];
    const float* w_un    = (const float*)d_in[11];
    const float* wd_un   = (const float*)d_in[12];

    cudaMemcpyToSymbolAsync(c_wvn,  w_vn,  48*sizeof(float), 0, cudaMemcpyDeviceToDevice, 0);
    cudaMemcpyToSymbolAsync(c_wdvn, wd_vn, 48*sizeof(float), 0, cudaMemcpyDeviceToDevice, 0);
    cudaMemcpyToSymbolAsync(c_wh1,  w_h1, 128*sizeof(float), 0, cudaMemcpyDeviceToDevice, 0);
    cudaMemcpyToSymbolAsync(c_wh2,  w_h2,  64*sizeof(float), 0, cudaMemcpyDeviceToDevice, 0);
    cudaMemcpyToSymbolAsync(c_bh2,  b_h2,   8*sizeof(float), 0, cudaMemcpyDeviceToDevice, 0);
    prep_wuni<<<8, 256>>>(w_un, wd_un);

    const int N = in_sizes[0] / 3;
    const int per_block = WARPS * PTS;
    const int blocks = (N + per_block - 1) / per_block;
    arek<<<blocks, 128>>>(q_pts, s_pts, nbr, wb, wd_relu, (float*)d_out, N);
}

// round 10
// speedup vs baseline: 1.0417x; 1.0417x over previous
#include <cuda_runtime.h>

typedef unsigned long long u64;
#define WARPS 4
#define PTS 2
#define FULLMASK 0xffffffffu

// combined constant bank: [0,48) w_vn | [48,96) wd_vn | [96,224) w_h1 |
//                         [224,288) w_h2 | [288,296) b_h2
__constant__ __align__(16) float c_all[304];
__device__ __align__(16) float g_stage[304];
__device__ float2 g_wuni[2048];   // interleaved {w_un, wd_un}

__global__ void prep(const float* __restrict__ w_un, const float* __restrict__ wd_un,
                     const float* __restrict__ w_vn, const float* __restrict__ wd_vn,
                     const float* __restrict__ w_h1, const float* __restrict__ w_h2,
                     const float* __restrict__ b_h2) {
    const int i = blockIdx.x * blockDim.x + threadIdx.x;
    if (i < 2048) g_wuni[i] = make_float2(w_un[i], wd_un[i]);
    if (i < 48)               g_stage[i]       = w_vn[i];
    else if (i < 96)          g_stage[i]       = wd_vn[i - 48];
    else if (i < 224)         g_stage[i]       = w_h1[i - 96];
    else if (i < 288)         g_stage[i]       = w_h2[i - 224];
    else if (i < 296)         g_stage[i]       = b_h2[i - 288];
}

__device__ __forceinline__ u64 pk2(float x, float y) {
    u64 r; asm("mov.b64 %0,{%1,%2};" : "=l"(r) : "f"(x), "f"(y)); return r;
}
__device__ __forceinline__ void upk2(u64 v, float& x, float& y) {
    asm("mov.b64 {%0,%1},%2;" : "=f"(x), "=f"(y) : "l"(v));
}
__device__ __forceinline__ u64 fma2(u64 a, u64 b, u64 c) {
    u64 d; asm("fma.rn.f32x2 %0,%1,%2,%3;" : "=l"(d) : "l"(a), "l"(b), "l"(c)); return d;
}
__device__ __forceinline__ u64 mul2(u64 a, u64 b) {
    u64 d; asm("mul.rn.f32x2 %0,%1,%2;" : "=l"(d) : "l"(a), "l"(b)); return d;
}
__device__ __forceinline__ u64 add2(u64 a, u64 b) {
    u64 d; asm("add.rn.f32x2 %0,%1,%2;" : "=l"(d) : "l"(a), "l"(b)); return d;
}

__global__ void __launch_bounds__(128, 6) arek(
    const float* __restrict__ q_pts, const float* __restrict__ s_pts,
    const int*   __restrict__ nbr,
    const float* __restrict__ wb,
    const float* __restrict__ wd_relu,
    float* __restrict__ out, int N)
{
    const float BN = 0.99999500003749968f;   // 1/sqrt(1+1e-5)
    const float BN2 = BN * BN;

    __shared__ float s_wb[768];
    __shared__ __align__(16) u64 s_local2[WARPS][16][10];  // comps 0..8 = p,c,r xyz
    __shared__ __align__(16) u64 s_score2[WARPS][16][10];  // comps 0..7 = scores (unnormalized)
    __shared__ u64 s_feat2 [WARPS][32][3];                 // [h][comp] -> (p0,p1)

    const int tid = threadIdx.x;
    #pragma unroll
    for (int i = tid; i < 768; i += 128) s_wb[i] = wb[i];
    __syncthreads();

    const int warp = tid >> 5, lane = tid & 31;
    const int n0 = blockIdx.x * (WARPS * PTS) + warp * PTS;
    if (n0 >= N) return;

    // ================= Phase 1: lane = (p, k), channel-pair packed =================
    {
        const int pp = lane >> 4;            // point within pair
        const int k  = lane & 15;            // neighbor
        const int n  = (n0 + pp < N) ? (n0 + pp) : (N - 1);

        const float qx = q_pts[n*3+0], qy = q_pts[n*3+1], qz = q_pts[n*3+2];
        const int idx = nbr[n*16 + k];
        const float px = s_pts[idx*3+0] - qx;
        const float py = s_pts[idx*3+1] - qy;
        const float pz = s_pts[idx*3+2] - qz;

        float sx = px, sy = py, sz = pz;
        #pragma unroll
        for (int off = 1; off < 16; off <<= 1) {
            sx += __shfl_xor_sync(FULLMASK, sx, off);
            sy += __shfl_xor_sync(FULLMASK, sy, off);
            sz += __shfl_xor_sync(FULLMASK, sz, off);
        }
        const float cx = sx * (1.0f/16.0f);
        const float cy = sy * (1.0f/16.0f);
        const float cz = sz * (1.0f/16.0f);

        const float rx = py*cz - pz*cy;
        const float ry = pz*cx - px*cz;
        const float rz = px*cy - py*cx;

        ((float*)&s_local2[warp][k][0])[pp] = px;
        ((float*)&s_local2[warp][k][1])[pp] = py;
        ((float*)&s_local2[warp][k][2])[pp] = pz;
        ((float*)&s_local2[warp][k][3])[pp] = cx;
        ((float*)&s_local2[warp][k][4])[pp] = cy;
        ((float*)&s_local2[warp][k][5])[pp] = cz;
        ((float*)&s_local2[warp][k][6])[pp] = rx;
        ((float*)&s_local2[warp][k][7])[pp] = ry;
        ((float*)&s_local2[warp][k][8])[pp] = rz;

        const u64 PX = pk2(px,px), PY = pk2(py,py), PZ = pk2(pz,pz);
        const u64 CX = pk2(cx,cx), CY = pk2(cy,cy), CZ = pk2(cz,cz);
        const u64 RX = pk2(rx,rx), RY = pk2(ry,ry), RZ = pk2(rz,rz);

        // h1 accum over o-pairs; channel loop packed over (2pc, 2pc+1); BN^2 folded at end
        u64 h1p[4] = {0,0,0,0};
        #pragma unroll
        for (int pc = 0; pc < 8; pc++) {
            const u64 wA = *(const u64*)&c_all[      2*pc];
            const u64 wB = *(const u64*)&c_all[16  + 2*pc];
            const u64 wC = *(const u64*)&c_all[32  + 2*pc];
            const u64 uA = *(const u64*)&c_all[48  + 2*pc];
            const u64 uB = *(const u64*)&c_all[64  + 2*pc];
            const u64 uC = *(const u64*)&c_all[80  + 2*pc];
            const u64 p0 = fma2(PX, wA, fma2(CX, wB, mul2(RX, wC)));
            const u64 p1 = fma2(PY, wA, fma2(CY, wB, mul2(RY, wC)));
            const u64 p2 = fma2(PZ, wA, fma2(CZ, wB, mul2(RZ, wC)));
            const u64 d0 = fma2(PX, uA, fma2(CX, uB, mul2(RX, uC)));
            const u64 d1 = fma2(PY, uA, fma2(CY, uB, mul2(RY, uC)));
            const u64 d2 = fma2(PZ, uA, fma2(CZ, uB, mul2(RZ, uC)));
            const u64 dot2 = fma2(p0, d0, fma2(p1, d1, mul2(p2, d2)));
            const u64 dsq2 = fma2(d0, d0, fma2(d1, d1, mul2(d2, d2)));
            float dta, dtb, dqa, dqb;
            upk2(dot2, dta, dtb); upk2(dsq2, dqa, dqb);
            const float nfa = (dta >= 0.0f) ? 0.0f : (-0.8f * __fdividef(dta, dqa + 1e-6f));
            const float nfb = (dtb >= 0.0f) ? 0.0f : (-0.8f * __fdividef(dtb, dqb + 1e-6f));
            const u64 nf = pk2(nfa, nfb);
            const u64 s0 = fma2(nf, d0, p0);
            const u64 s1 = fma2(nf, d1, p1);
            const u64 s2 = fma2(nf, d2, p2);
            const u64 nn = fma2(s0, s0, fma2(s1, s1, mul2(s2, s2)));
            float na, nb; upk2(nn, na, nb);
            const float sa = sqrtf(na), sb = sqrtf(nb);
            const u64 SA = pk2(sa, sa), SB = pk2(sb, sb);
            const ulonglong2* r0 = (const ulonglong2*)&c_all[96 + (2*pc  )*8];
            const ulonglong2* r1 = (const ulonglong2*)&c_all[96 + (2*pc+1)*8];
            const ulonglong2 r0a = r0[0], r0b = r0[1];
            const ulonglong2 r1a = r1[0], r1b = r1[1];
            h1p[0] = fma2(SA, r0a.x, fma2(SB, r1a.x, h1p[0]));
            h1p[1] = fma2(SA, r0a.y, fma2(SB, r1a.y, h1p[1]));
            h1p[2] = fma2(SA, r0b.x, fma2(SB, r1b.x, h1p[2]));
            h1p[3] = fma2(SA, r0b.y, fma2(SB, r1b.y, h1p[3]));
        }
        const u64 BN2d = pk2(BN2, BN2);
        float h1s[8];
        #pragma unroll
        for (int o2 = 0; o2 < 4; o2++) {
            float ea, eb; upk2(mul2(h1p[o2], BN2d), ea, eb);
            h1s[2*o2]   = fmaxf(0.0f, ea);
            h1s[2*o2+1] = fmaxf(0.0f, eb);
        }

        // h2 accum over o-pairs
        u64 h2p[4] = { *(const u64*)&c_all[288], *(const u64*)&c_all[290],
                       *(const u64*)&c_all[292], *(const u64*)&c_all[294] };
        #pragma unroll
        for (int c = 0; c < 8; c++) {
            const ulonglong2* wr = (const ulonglong2*)&c_all[224 + c*8];
            const ulonglong2 wa = wr[0], wbq = wr[1];
            const u64 SC = pk2(h1s[c], h1s[c]);
            h2p[0] = fma2(SC, wa.x,  h2p[0]);
            h2p[1] = fma2(SC, wa.y,  h2p[1]);
            h2p[2] = fma2(SC, wbq.x, h2p[2]);
            h2p[3] = fma2(SC, wbq.y, h2p[3]);
        }
        float h2[8];
        upk2(h2p[0], h2[0], h2[1]); upk2(h2p[1], h2[2], h2[3]);
        upk2(h2p[2], h2[4], h2[5]); upk2(h2p[3], h2[6], h2[7]);
        float m = h2[0];
        #pragma unroll
        for (int o = 1; o < 8; o++) m = fmaxf(m, h2[o]);
        // softmax denominator cancels in phase-2 per-k normalization
        #pragma unroll
        for (int o = 0; o < 8; o++)
            ((float*)&s_score2[warp][k][o])[pp] = __expf(h2[o] - m);
    }
    __syncwarp();

    // ======= Phase 2: correlation, lane = channel h, packed over the 2 points =======
    u64 wbd0[8], wbd1[8], wbd2[8];
    #pragma unroll
    for (int ks = 0; ks < 8; ks++) {
        const float w0 = s_wb[      ks*32 + lane];
        const float w1 = s_wb[256 + ks*32 + lane];
        const float w2 = s_wb[512 + ks*32 + lane];
        wbd0[ks] = pk2(w0, w0); wbd1[ks] = pk2(w1, w1); wbd2[ks] = pk2(w2, w2);
    }
    {
        u64 fa0 = 0, fa1 = 0, fa2 = 0;
        #pragma unroll
        for (int kk = 0; kk < 16; kk++) {
            const ulonglong2* scv = (const ulonglong2*)s_score2[warp][kk];
            const ulonglong2 sAB = scv[0], sCD = scv[1], sEF = scv[2], sGH = scv[3];
            // split chains: even-ks and odd-ks halves (depth 4 each) then combine
            u64 e0 = mul2(sAB.x, wbd0[0]), o0 = mul2(sAB.y, wbd0[1]);
            u64 e1 = mul2(sAB.x, wbd1[0]), o1 = mul2(sAB.y, wbd1[1]);
            u64 e2 = mul2(sAB.x, wbd2[0]), o2 = mul2(sAB.y, wbd2[1]);
            e0 = fma2(sCD.x, wbd0[2], e0); o0 = fma2(sCD.y, wbd0[3], o0);
            e1 = fma2(sCD.x, wbd1[2], e1); o1 = fma2(sCD.y, wbd1[3], o1);
            e2 = fma2(sCD.x, wbd2[2], e2); o2 = fma2(sCD.y, wbd2[3], o2);
            e0 = fma2(sEF.x, wbd0[4], e0); o0 = fma2(sEF.y, wbd0[5], o0);
            e1 = fma2(sEF.x, wbd1[4], e1); o1 = fma2(sEF.y, wbd1[5], o1);
            e2 = fma2(sEF.x, wbd2[4], e2); o2 = fma2(sEF.y, wbd2[5], o2);
            e0 = fma2(sGH.x, wbd0[6], e0); o0 = fma2(sGH.y, wbd0[7], o0);
            e1 = fma2(sGH.x, wbd1[6], e1); o1 = fma2(sGH.y, wbd1[7], o1);
            e2 = fma2(sGH.x, wbd2[6], e2); o2 = fma2(sGH.y, wbd2[7], o2);
            const u64 we0 = add2(e0, o0);
            const u64 we1 = add2(e1, o1);
            const u64 we2 = add2(e2, o2);

            const ulonglong2* Lv = (const ulonglong2*)s_local2[warp][kk];
            const ulonglong2 L01 = Lv[0], L23 = Lv[1], L45 = Lv[2], L67 = Lv[3];
            const u64 L8 = s_local2[warp][kk][8];
            const u64 q0 = fma2(L01.x, we0, fma2(L23.y, we1, mul2(L67.x, we2)));
            const u64 q1 = fma2(L01.y, we0, fma2(L45.x, we1, mul2(L67.y, we2)));
            const u64 q2 = fma2(L23.x, we0, fma2(L45.y, we1, mul2(L8,    we2)));
            const u64 nn = fma2(q0, q0, fma2(q1, q1, mul2(q2, q2)));
            float n0f, n1f; upk2(nn, n0f, n1f);
            const u64 iv = pk2(rsqrtf(fmaxf(n0f, 1e-24f)), rsqrtf(fmaxf(n1f, 1e-24f)));
            fa0 = fma2(q0, iv, fa0);
            fa1 = fma2(q1, iv, fa1);
            fa2 = fma2(q2, iv, fa2);
        }
        const u64 SC = pk2(1.0f/16.0f, 1.0f/16.0f);
        s_feat2[warp][lane][0] = mul2(fa0, SC);
        s_feat2[warp][lane][1] = mul2(fa1, SC);
        s_feat2[warp][lane][2] = mul2(fa2, SC);
    }
    __syncwarp();

    // ======= Phase 3a: VNLeakyReLU(32->32), packed over points =======
    {
        u64 f0 = s_feat2[warp][lane][0];
        u64 f1 = s_feat2[warp][lane][1];
        u64 f2 = s_feat2[warp][lane][2];
        u64 g0 = 0, g1 = 0, g2 = 0;
        #pragma unroll
        for (int h = 0; h < 32; h++) {
            const float w = __ldg(wd_relu + h*32 + lane);
            const u64 w2 = pk2(w, w);
            g0 = fma2(s_feat2[warp][h][0], w2, g0);
            g1 = fma2(s_feat2[warp][h][1], w2, g1);
            g2 = fma2(s_feat2[warp][h][2], w2, g2);
        }
        const u64 dot2 = fma2(f0, g0, fma2(f1, g1, mul2(f2, g2)));
        const u64 dsq2 = fma2(g0, g0, fma2(g1, g1, mul2(g2, g2)));
        float dta, dtb, dqa, dqb;
        upk2(dot2, dta, dtb); upk2(dsq2, dqa, dqb);
        const float nfa = (dta >= 0.0f) ? 0.0f : (-0.8f * __fdividef(dta, dqa + 1e-6f));
        const float nfb = (dtb >= 0.0f) ? 0.0f : (-0.8f * __fdividef(dtb, dqb + 1e-6f));
        const u64 nf = pk2(nfa, nfb);
        __syncwarp();
        s_feat2[warp][lane][0] = fma2(nf, g0, f0);
        s_feat2[warp][lane][1] = fma2(nf, g1, f1);
        s_feat2[warp][lane][2] = fma2(nf, g2, f2);
    }
    __syncwarp();

    // ======= Phase 3b: VNLinearLeakyReLU(32->64), interleaved weights, packed =======
    {
        u64 ax=0, ay=0, az=0, bx=0, by=0, bz=0;   // j = lane
        u64 Ax=0, Ay=0, Az=0, Bx=0, By=0, Bz=0;   // j = lane + 32
        #pragma unroll
        for (int h = 0; h < 32; h++) {
            const float2 wv0 = g_wuni[h*64 + lane];
            const float2 wv1 = g_wuni[h*64 + lane + 32];
            const u64 F0 = s_feat2[warp][h][0];
            const u64 F1 = s_feat2[warp][h][1];
            const u64 F2 = s_feat2[warp][h][2];
            const u64 wa0d = pk2(wv0.x, wv0.x), wd0d = pk2(wv0.y, wv0.y);
            const u64 wa1d = pk2(wv1.x, wv1.x), wd1d = pk2(wv1.y, wv1.y);
            ax = fma2(F0, wa0d, ax); ay = fma2(F1, wa0d, ay); az = fma2(F2, wa0d, az);
            bx = fma2(F0, wd0d, bx); by = fma2(F1, wd0d, by); bz = fma2(F2, wd0d, bz);
            Ax = fma2(F0, wa1d, Ax); Ay = fma2(F1, wa1d, Ay); Az = fma2(F2, wa1d, Az);
            Bx = fma2(F0, wd1d, Bx); By = fma2(F1, wd1d, By); Bz = fma2(F2, wd1d, Bz);
        }
        float axp[2], ayp[2], azp[2], bxp[2], byp[2], bzp[2];
        float Axp[2], Ayp[2], Azp[2], Bxp[2], Byp[2], Bzp[2];
        upk2(ax, axp[0], axp[1]); upk2(ay, ayp[0], ayp[1]); upk2(az, azp[0], azp[1]);
        upk2(bx, bxp[0], bxp[1]); upk2(by, byp[0], byp[1]); upk2(bz, bzp[0], bzp[1]);
        upk2(Ax, Axp[0], Axp[1]); upk2(Ay, Ayp[0], Ayp[1]); upk2(Az, Azp[0], Azp[1]);
        upk2(Bx, Bxp[0], Bxp[1]); upk2(By, Byp[0], Byp[1]); upk2(Bz, Bzp[0], Bzp[1]);
        #pragma unroll
        for (int p = 0; p < PTS; p++) {
            if (n0 + p >= N) break;
            const int n = n0 + p;
            {
                const int j = lane;
                const float x0 = BN*axp[p], x1 = BN*ayp[p], x2 = BN*azp[p];
                const float dt = x0*bxp[p] + x1*byp[p] + x2*bzp[p];
                const float dq = bxp[p]*bxp[p] + byp[p]*byp[p] + bzp[p]*bzp[p];
                const float fc = (dt >= 0.0f) ? 0.0f : (0.8f * __fdividef(dt, dq + 1e-6f));
                out[n*192 + j*3 + 0] = x0 - fc*bxp[p];
                out[n*192 + j*3 + 1] = x1 - fc*byp[p];
                out[n*192 + j*3 + 2] = x2 - fc*bzp[p];
            }
            {
                const int j = lane + 32;
                const float x0 = BN*Axp[p], x1 = BN*Ayp[p], x2 = BN*Azp[p];
                const float dt = x0*Bxp[p] + x1*Byp[p] + x2*Bzp[p];
                const float dq = Bxp[p]*Bxp[p] + Byp[p]*Byp[p] + Bzp[p]*Bzp[p];
                const float fc = (dt >= 0.0f) ? 0.0f : (0.8f * __fdividef(dt, dq + 1e-6f));
                out[n*192 + j*3 + 0] = x0 - fc*Bxp[p];
                out[n*192 + j*3 + 1] = x1 - fc*Byp[p];
                out[n*192 + j*3 + 2] = x2 - fc*Bzp[p];
            }
        }
    }
}

extern "C" void kernel_launch(void* const* d_in, const int* in_sizes, int n_in,
                              void* d_out, int out_size) {
    const float* q_pts   = (const float*)d_in[0];
    const float* s_pts   = (const float*)d_in[1];
    const int*   nbr     = (const int*)  d_in[3];
    const float* wb      = (const float*)d_in[4];
    const float* w_vn    = (const float*)d_in[5];
    const float* wd_vn   = (const float*)d_in[6];
    const float* w_h1    = (const float*)d_in[7];
    const float* w_h2    = (const float*)d_in[8];
    const float* b_h2    = (const float*)d_in[9];
    const float* wd_relu = (const float*)d_in[10];
    const float* w_un    = (const float*)d_in[11];
    const float* wd_un   = (const float*)d_in[12];

    prep<<<8, 256>>>(w_un, wd_un, w_vn, wd_vn, w_h1, w_h2, b_h2);

    void* stage_ptr = nullptr;
    cudaGetSymbolAddress(&stage_ptr, g_stage);
    cudaMemcpyToSymbolAsync(c_all, stage_ptr, 296 * sizeof(float), 0,
                            cudaMemcpyDeviceToDevice, 0);

    const int N = in_sizes[0] / 3;
    const int per_block = WARPS * PTS;
    const int blocks = (N + per_block - 1) / per_block;
    arek<<<blocks, 128>>>(q_pts, s_pts, nbr, wb, wd_relu, (float*)d_out, N);
}

// round 11
// speedup vs baseline: 1.0980x; 1.0540x over previous
#include <cuda_runtime.h>

typedef unsigned long long u64;
#define WARPS 4
#define PTS 2
#define FULLMASK 0xffffffffu

// combined constant bank: [0,48) w_vn | [48,96) wd_vn | [96,224) w_h1 |
//                         [224,288) w_h2 | [288,296) b_h2
__constant__ __align__(16) float c_all[304];
__device__ __align__(16) float g_stage[304];
__device__ float2 g_wuni[2048];   // interleaved {w_un, wd_un}

__global__ void prep(const float* __restrict__ w_un, const float* __restrict__ wd_un,
                     const float* __restrict__ w_vn, const float* __restrict__ wd_vn,
                     const float* __restrict__ w_h1, const float* __restrict__ w_h2,
                     const float* __restrict__ b_h2) {
    const int i = blockIdx.x * blockDim.x + threadIdx.x;
    if (i < 2048) g_wuni[i] = make_float2(w_un[i], wd_un[i]);
    if (i < 48)               g_stage[i]       = w_vn[i];
    else if (i < 96)          g_stage[i]       = wd_vn[i - 48];
    else if (i < 224)         g_stage[i]       = w_h1[i - 96];
    else if (i < 288)         g_stage[i]       = w_h2[i - 224];
    else if (i < 296)         g_stage[i]       = b_h2[i - 288];
}

__device__ __forceinline__ u64 pk2(float x, float y) {
    u64 r; asm("mov.b64 %0,{%1,%2};" : "=l"(r) : "f"(x), "f"(y)); return r;
}
__device__ __forceinline__ void upk2(u64 v, float& x, float& y) {
    asm("mov.b64 {%0,%1},%2;" : "=f"(x), "=f"(y) : "l"(v));
}
__device__ __forceinline__ u64 fma2(u64 a, u64 b, u64 c) {
    u64 d; asm("fma.rn.f32x2 %0,%1,%2,%3;" : "=l"(d) : "l"(a), "l"(b), "l"(c)); return d;
}
__device__ __forceinline__ u64 mul2(u64 a, u64 b) {
    u64 d; asm("mul.rn.f32x2 %0,%1,%2;" : "=l"(d) : "l"(a), "l"(b)); return d;
}

__global__ void __launch_bounds__(128, 6) arek(
    const float* __restrict__ q_pts, const float* __restrict__ s_pts,
    const int*   __restrict__ nbr,
    const float* __restrict__ wb,
    const float* __restrict__ wd_relu,
    float* __restrict__ out, int N)
{
    const float BN = 0.99999500003749968f;   // 1/sqrt(1+1e-5)
    const float BN2 = BN * BN;

    __shared__ float s_wb[768];
    __shared__ __align__(16) u64 s_local2[WARPS][16][10];  // comps 0..8 = p,c,r xyz
    __shared__ __align__(16) u64 s_score2[WARPS][16][10];  // comps 0..7 = scores (unnormalized)
    __shared__ u64 s_feat2 [WARPS][32][3];                 // [h][comp] -> (p0,p1)

    const int tid = threadIdx.x;
    #pragma unroll
    for (int i = tid; i < 768; i += 128) s_wb[i] = wb[i];
    __syncthreads();

    const int warp = tid >> 5, lane = tid & 31;
    const int n0 = blockIdx.x * (WARPS * PTS) + warp * PTS;
    if (n0 >= N) return;

    // ================= Phase 1: lane = (p, k), channel-pair packed =================
    {
        const int pp = lane >> 4;            // point within pair
        const int k  = lane & 15;            // neighbor
        const int n  = (n0 + pp < N) ? (n0 + pp) : (N - 1);

        const float qx = q_pts[n*3+0], qy = q_pts[n*3+1], qz = q_pts[n*3+2];
        const int idx = nbr[n*16 + k];
        const float px = s_pts[idx*3+0] - qx;
        const float py = s_pts[idx*3+1] - qy;
        const float pz = s_pts[idx*3+2] - qz;

        float sx = px, sy = py, sz = pz;
        #pragma unroll
        for (int off = 1; off < 16; off <<= 1) {
            sx += __shfl_xor_sync(FULLMASK, sx, off);
            sy += __shfl_xor_sync(FULLMASK, sy, off);
            sz += __shfl_xor_sync(FULLMASK, sz, off);
        }
        const float cx = sx * (1.0f/16.0f);
        const float cy = sy * (1.0f/16.0f);
        const float cz = sz * (1.0f/16.0f);

        const float rx = py*cz - pz*cy;
        const float ry = pz*cx - px*cz;
        const float rz = px*cy - py*cx;

        ((float*)&s_local2[warp][k][0])[pp] = px;
        ((float*)&s_local2[warp][k][1])[pp] = py;
        ((float*)&s_local2[warp][k][2])[pp] = pz;
        ((float*)&s_local2[warp][k][3])[pp] = cx;
        ((float*)&s_local2[warp][k][4])[pp] = cy;
        ((float*)&s_local2[warp][k][5])[pp] = cz;
        ((float*)&s_local2[warp][k][6])[pp] = rx;
        ((float*)&s_local2[warp][k][7])[pp] = ry;
        ((float*)&s_local2[warp][k][8])[pp] = rz;

        const u64 PX = pk2(px,px), PY = pk2(py,py), PZ = pk2(pz,pz);
        const u64 CX = pk2(cx,cx), CY = pk2(cy,cy), CZ = pk2(cz,cz);
        const u64 RX = pk2(rx,rx), RY = pk2(ry,ry), RZ = pk2(rz,rz);

        // h1 accum over o-pairs; channel loop packed over (2pc, 2pc+1); BN^2 folded at end
        u64 h1p[4] = {0,0,0,0};
        #pragma unroll
        for (int pc = 0; pc < 8; pc++) {
            const u64 wA = *(const u64*)&c_all[      2*pc];
            const u64 wB = *(const u64*)&c_all[16  + 2*pc];
            const u64 wC = *(const u64*)&c_all[32  + 2*pc];
            const u64 uA = *(const u64*)&c_all[48  + 2*pc];
            const u64 uB = *(const u64*)&c_all[64  + 2*pc];
            const u64 uC = *(const u64*)&c_all[80  + 2*pc];
            const u64 p0 = fma2(PX, wA, fma2(CX, wB, mul2(RX, wC)));
            const u64 p1 = fma2(PY, wA, fma2(CY, wB, mul2(RY, wC)));
            const u64 p2 = fma2(PZ, wA, fma2(CZ, wB, mul2(RZ, wC)));
            const u64 d0 = fma2(PX, uA, fma2(CX, uB, mul2(RX, uC)));
            const u64 d1 = fma2(PY, uA, fma2(CY, uB, mul2(RY, uC)));
            const u64 d2 = fma2(PZ, uA, fma2(CZ, uB, mul2(RZ, uC)));
            const u64 dot2 = fma2(p0, d0, fma2(p1, d1, mul2(p2, d2)));
            const u64 dsq2 = fma2(d0, d0, fma2(d1, d1, mul2(d2, d2)));
            float dta, dtb, dqa, dqb;
            upk2(dot2, dta, dtb); upk2(dsq2, dqa, dqb);
            const float nfa = (dta >= 0.0f) ? 0.0f : (-0.8f * __fdividef(dta, dqa + 1e-6f));
            const float nfb = (dtb >= 0.0f) ? 0.0f : (-0.8f * __fdividef(dtb, dqb + 1e-6f));
            const u64 nf = pk2(nfa, nfb);
            const u64 s0 = fma2(nf, d0, p0);
            const u64 s1 = fma2(nf, d1, p1);
            const u64 s2 = fma2(nf, d2, p2);
            const u64 nn = fma2(s0, s0, fma2(s1, s1, mul2(s2, s2)));
            float na, nb; upk2(nn, na, nb);
            const float sa = sqrtf(na), sb = sqrtf(nb);
            const u64 SA = pk2(sa, sa), SB = pk2(sb, sb);
            const ulonglong2* r0 = (const ulonglong2*)&c_all[96 + (2*pc  )*8];
            const ulonglong2* r1 = (const ulonglong2*)&c_all[96 + (2*pc+1)*8];
            const ulonglong2 r0a = r0[0], r0b = r0[1];
            const ulonglong2 r1a = r1[0], r1b = r1[1];
            h1p[0] = fma2(SA, r0a.x, fma2(SB, r1a.x, h1p[0]));
            h1p[1] = fma2(SA, r0a.y, fma2(SB, r1a.y, h1p[1]));
            h1p[2] = fma2(SA, r0b.x, fma2(SB, r1b.x, h1p[2]));
            h1p[3] = fma2(SA, r0b.y, fma2(SB, r1b.y, h1p[3]));
        }
        const u64 BN2d = pk2(BN2, BN2);
        float h1s[8];
        #pragma unroll
        for (int o2 = 0; o2 < 4; o2++) {
            float ea, eb; upk2(mul2(h1p[o2], BN2d), ea, eb);
            h1s[2*o2]   = fmaxf(0.0f, ea);
            h1s[2*o2+1] = fmaxf(0.0f, eb);
        }

        // h2 accum over o-pairs
        u64 h2p[4] = { *(const u64*)&c_all[288], *(const u64*)&c_all[290],
                       *(const u64*)&c_all[292], *(const u64*)&c_all[294] };
        #pragma unroll
        for (int c = 0; c < 8; c++) {
            const ulonglong2* wr = (const ulonglong2*)&c_all[224 + c*8];
            const ulonglong2 wa = wr[0], wbq = wr[1];
            const u64 SC = pk2(h1s[c], h1s[c]);
            h2p[0] = fma2(SC, wa.x,  h2p[0]);
            h2p[1] = fma2(SC, wa.y,  h2p[1]);
            h2p[2] = fma2(SC, wbq.x, h2p[2]);
            h2p[3] = fma2(SC, wbq.y, h2p[3]);
        }
        float h2[8];
        upk2(h2p[0], h2[0], h2[1]); upk2(h2p[1], h2[2], h2[3]);
        upk2(h2p[2], h2[4], h2[5]); upk2(h2p[3], h2[6], h2[7]);
        float m = h2[0];
        #pragma unroll
        for (int o = 1; o < 8; o++) m = fmaxf(m, h2[o]);
        // softmax denominator cancels in phase-2 per-k normalization
        #pragma unroll
        for (int o = 0; o < 8; o++)
            ((float*)&s_score2[warp][k][o])[pp] = __expf(h2[o] - m);
    }
    __syncwarp();

    // ======= Phase 2: correlation, lane = channel h, packed over the 2 points =======
    u64 wbd0[8], wbd1[8], wbd2[8];
    #pragma unroll
    for (int ks = 0; ks < 8; ks++) {
        const float w0 = s_wb[      ks*32 + lane];
        const float w1 = s_wb[256 + ks*32 + lane];
        const float w2 = s_wb[512 + ks*32 + lane];
        wbd0[ks] = pk2(w0, w0); wbd1[ks] = pk2(w1, w1); wbd2[ks] = pk2(w2, w2);
    }
    {
        u64 fa0 = 0, fa1 = 0, fa2 = 0;
        #pragma unroll
        for (int kk = 0; kk < 16; kk++) {
            const ulonglong2* scv = (const ulonglong2*)s_score2[warp][kk];
            const ulonglong2 sAB = scv[0], sCD = scv[1], sEF = scv[2], sGH = scv[3];
            u64 we0 = mul2(sAB.x, wbd0[0]);
            u64 we1 = mul2(sAB.x, wbd1[0]);
            u64 we2 = mul2(sAB.x, wbd2[0]);
            we0 = fma2(sAB.y, wbd0[1], we0); we1 = fma2(sAB.y, wbd1[1], we1); we2 = fma2(sAB.y, wbd2[1], we2);
            we0 = fma2(sCD.x, wbd0[2], we0); we1 = fma2(sCD.x, wbd1[2], we1); we2 = fma2(sCD.x, wbd2[2], we2);
            we0 = fma2(sCD.y, wbd0[3], we0); we1 = fma2(sCD.y, wbd1[3], we1); we2 = fma2(sCD.y, wbd2[3], we2);
            we0 = fma2(sEF.x, wbd0[4], we0); we1 = fma2(sEF.x, wbd1[4], we1); we2 = fma2(sEF.x, wbd2[4], we2);
            we0 = fma2(sEF.y, wbd0[5], we0); we1 = fma2(sEF.y, wbd1[5], we1); we2 = fma2(sEF.y, wbd2[5], we2);
            we0 = fma2(sGH.x, wbd0[6], we0); we1 = fma2(sGH.x, wbd1[6], we1); we2 = fma2(sGH.x, wbd2[6], we2);
            we0 = fma2(sGH.y, wbd0[7], we0); we1 = fma2(sGH.y, wbd1[7], we1); we2 = fma2(sGH.y, wbd2[7], we2);

            const ulonglong2* Lv = (const ulonglong2*)s_local2[warp][kk];
            const ulonglong2 L01 = Lv[0], L23 = Lv[1], L45 = Lv[2], L67 = Lv[3];
            const u64 L8 = s_local2[warp][kk][8];
            const u64 q0 = fma2(L01.x, we0, fma2(L23.y, we1, mul2(L67.x, we2)));
            const u64 q1 = fma2(L01.y, we0, fma2(L45.x, we1, mul2(L67.y, we2)));
            const u64 q2 = fma2(L23.x, we0, fma2(L45.y, we1, mul2(L8,    we2)));
            const u64 nn = fma2(q0, q0, fma2(q1, q1, mul2(q2, q2)));
            float n0f, n1f; upk2(nn, n0f, n1f);
            const u64 iv = pk2(rsqrtf(fmaxf(n0f, 1e-24f)), rsqrtf(fmaxf(n1f, 1e-24f)));
            fa0 = fma2(q0, iv, fa0);
            fa1 = fma2(q1, iv, fa1);
            fa2 = fma2(q2, iv, fa2);
        }
        const u64 SC = pk2(1.0f/16.0f, 1.0f/16.0f);
        s_feat2[warp][lane][0] = mul2(fa0, SC);
        s_feat2[warp][lane][1] = mul2(fa1, SC);
        s_feat2[warp][lane][2] = mul2(fa2, SC);
    }
    __syncwarp();

    // ======= Phase 3a: VNLeakyReLU(32->32), packed over points =======
    {
        u64 f0 = s_feat2[warp][lane][0];
        u64 f1 = s_feat2[warp][lane][1];
        u64 f2 = s_feat2[warp][lane][2];
        u64 g0 = 0, g1 = 0, g2 = 0;
        #pragma unroll
        for (int h = 0; h < 32; h++) {
            const float w = __ldg(wd_relu + h*32 + lane);
            const u64 w2 = pk2(w, w);
            g0 = fma2(s_feat2[warp][h][0], w2, g0);
            g1 = fma2(s_feat2[warp][h][1], w2, g1);
            g2 = fma2(s_feat2[warp][h][2], w2, g2);
        }
        const u64 dot2 = fma2(f0, g0, fma2(f1, g1, mul2(f2, g2)));
        const u64 dsq2 = fma2(g0, g0, fma2(g1, g1, mul2(g2, g2)));
        float dta, dtb, dqa, dqb;
        upk2(dot2, dta, dtb); upk2(dsq2, dqa, dqb);
        const float nfa = (dta >= 0.0f) ? 0.0f : (-0.8f * __fdividef(dta, dqa + 1e-6f));
        const float nfb = (dtb >= 0.0f) ? 0.0f : (-0.8f * __fdividef(dtb, dqb + 1e-6f));
        const u64 nf = pk2(nfa, nfb);
        __syncwarp();
        s_feat2[warp][lane][0] = fma2(nf, g0, f0);
        s_feat2[warp][lane][1] = fma2(nf, g1, f1);
        s_feat2[warp][lane][2] = fma2(nf, g2, f2);
    }
    __syncwarp();

    // ======= Phase 3b: VNLinearLeakyReLU(32->64), interleaved weights, packed =======
    {
        u64 ax=0, ay=0, az=0, bx=0, by=0, bz=0;   // j = lane
        u64 Ax=0, Ay=0, Az=0, Bx=0, By=0, Bz=0;   // j = lane + 32
        #pragma unroll
        for (int h = 0; h < 32; h++) {
            const float2 wv0 = g_wuni[h*64 + lane];
            const float2 wv1 = g_wuni[h*64 + lane + 32];
            const u64 F0 = s_feat2[warp][h][0];
            const u64 F1 = s_feat2[warp][h][1];
            const u64 F2 = s_feat2[warp][h][2];
            const u64 wa0d = pk2(wv0.x, wv0.x), wd0d = pk2(wv0.y, wv0.y);
            const u64 wa1d = pk2(wv1.x, wv1.x), wd1d = pk2(wv1.y, wv1.y);
            ax = fma2(F0, wa0d, ax); ay = fma2(F1, wa0d, ay); az = fma2(F2, wa0d, az);
            bx = fma2(F0, wd0d, bx); by = fma2(F1, wd0d, by); bz = fma2(F2, wd0d, bz);
            Ax = fma2(F0, wa1d, Ax); Ay = fma2(F1, wa1d, Ay); Az = fma2(F2, wa1d, Az);
            Bx = fma2(F0, wd1d, Bx); By = fma2(F1, wd1d, By); Bz = fma2(F2, wd1d, Bz);
        }
        float axp[2], ayp[2], azp[2], bxp[2], byp[2], bzp[2];
        float Axp[2], Ayp[2], Azp[2], Bxp[2], Byp[2], Bzp[2];
        upk2(ax, axp[0], axp[1]); upk2(ay, ayp[0], ayp[1]); upk2(az, azp[0], azp[1]);
        upk2(bx, bxp[0], bxp[1]); upk2(by, byp[0], byp[1]); upk2(bz, bzp[0], bzp[1]);
        upk2(Ax, Axp[0], Axp[1]); upk2(Ay, Ayp[0], Ayp[1]); upk2(Az, Azp[0], Azp[1]);
        upk2(Bx, Bxp[0], Bxp[1]); upk2(By, Byp[0], Byp[1]); upk2(Bz, Bzp[0], Bzp[1]);
        #pragma unroll
        for (int p = 0; p < PTS; p++) {
            if (n0 + p >= N) break;
            const int n = n0 + p;
            {
                const int j = lane;
                const float x0 = BN*axp[p], x1 = BN*ayp[p], x2 = BN*azp[p];
                const float dt = x0*bxp[p] + x1*byp[p] + x2*bzp[p];
                const float dq = bxp[p]*bxp[p] + byp[p]*byp[p] + bzp[p]*bzp[p];
                const float fc = (dt >= 0.0f) ? 0.0f : (0.8f * __fdividef(dt, dq + 1e-6f));
                out[n*192 + j*3 + 0] = x0 - fc*bxp[p];
                out[n*192 + j*3 + 1] = x1 - fc*byp[p];
                out[n*192 + j*3 + 2] = x2 - fc*bzp[p];
            }
            {
                const int j = lane + 32;
                const float x0 = BN*Axp[p], x1 = BN*Ayp[p], x2 = BN*Azp[p];
                const float dt = x0*Bxp[p] + x1*Byp[p] + x2*Bzp[p];
                const float dq = Bxp[p]*Bxp[p] + Byp[p]*Byp[p] + Bzp[p]*Bzp[p];
                const float fc = (dt >= 0.0f) ? 0.0f : (0.8f * __fdividef(dt, dq + 1e-6f));
                out[n*192 + j*3 + 0] = x0 - fc*Bxp[p];
                out[n*192 + j*3 + 1] = x1 - fc*Byp[p];
                out[n*192 + j*3 + 2] = x2 - fc*Bzp[p];
            }
        }
    }
}

extern "C" void kernel_launch(void* const* d_in, const int* in_sizes, int n_in,
                              void* d_out, int out_size) {
    const float* q_pts   = (const float*)d_in[0];
    const float* s_pts   = (const float*)d_in[1];
    const int*   nbr     = (const int*)  d_in[3];
    const float* wb      = (const float*)d_in[4];
    const float* w_vn    = (const float*)d_in[5];
    const float* wd_vn   = (const float*)d_in[6];
    const float* w_h1    = (const float*)d_in[7];
    const float* w_h2    = (const float*)d_in[8];
    const float* b_h2    = (const float*)d_in[9];
    const float* wd_relu = (const float*)d_in[10];
    const float* w_un    = (const float*)d_in[11];
    const float* wd_un   = (const float*)d_in[12];

    prep<<<8, 256>>>(w_un, wd_un, w_vn, wd_vn, w_h1, w_h2, b_h2);

    void* stage_ptr = nullptr;
    cudaGetSymbolAddress(&stage_ptr, g_stage);
    cudaMemcpyToSymbolAsync(c_all, stage_ptr, 296 * sizeof(float), 0,
                            cudaMemcpyDeviceToDevice, 0);

    const int N = in_sizes[0] / 3;
    const int per_block = WARPS * PTS;
    const int blocks = (N + per_block - 1) / per_block;
    arek<<<blocks, 128>>>(q_pts, s_pts, nbr, wb, wd_relu, (float*)d_out, N);
}